// round 14
// baseline (speedup 1.0000x reference)
#include <cuda_runtime.h>
#include <cuda_fp16.h>
#include <cstdint>
#include <math.h>

#define BB   64
#define HH   2048
#define HIN  66
#define TT   25
#define OUTD 66
#define G4   8192
#define NCTA 128
#define NTHR 544        // 16 consumer warps + 1 producer warp
#define NST  6
#define STAGE 32768     // 16KB act + 16KB weight (k=128 tile)
#define GS_OFF (NST * STAGE)
#define BAR_OFF (GS_OFF + 17408)
#define SMEM_BYTES (BAR_OFF + 256)
#define NT0  34         // 64-k granules cell0 (hh first: 0..31, ih: 32..33)
#define NT1  64         // 64-k granules cell1 (hh: 0..31, ih: 32..63)
#define NT0T 17
#define NTT  49
#define TILE_H 4096

// ---------------- device scratch ----------------
__device__ __align__(256) __half g_W0p[NCTA * NT0 * TILE_H];
__device__ __align__(256) __half g_W1p[NCTA * NT1 * TILE_H];
__device__ __align__(256) __half g_xT[2 * TILE_H];
__device__ __align__(256) __half g_h0Ta[32 * TILE_H], g_h0Tb[32 * TILE_H];
__device__ __align__(256) __half g_h1Ta[32 * TILE_H], g_h1Tb[32 * TILE_H];
__device__ __align__(256) __half g_h1lin[BB * HH];
__device__ __align__(256) __half g_fcwh[OUTD * HH];
__device__ __align__(256) float  g_bias0[G4], g_bias1[G4];
__device__ __align__(256) float  g_c0[BB * HH], g_c1[BB * HH];
__device__ unsigned g_barcnt;

__device__ __forceinline__ int swz_off(int row, int u, int e) {
    return row * 64 + ((u ^ (row & 7)) << 3) + e;
}

// ---------------- setup (W0 hh-first; W1 hh-first) ----------------
__global__ void setup_kernel(const float* __restrict__ inputs,
                             const float* __restrict__ hiddens,
                             const float* __restrict__ cells,
                             const float* __restrict__ W_ih0,
                             const float* __restrict__ W_hh0,
                             const float* __restrict__ b_ih0,
                             const float* __restrict__ b_hh0,
                             const float* __restrict__ W_ih1,
                             const float* __restrict__ W_hh1,
                             const float* __restrict__ b_ih1,
                             const float* __restrict__ b_hh1,
                             const float* __restrict__ fc_w) {
    int i = blockIdx.x * blockDim.x + threadIdx.x;
    if (i == 0) g_barcnt = 0;

    const int S1 = NCTA * NT0 * 512;
    if (i < S1) {
        int bn = i / (NT0 * 512), r1 = i % (NT0 * 512);
        int T = r1 / 512, r2 = r1 & 511;
        int jj = r2 >> 3, u = r2 & 7;
        int R = (jj >> 4) * HH + bn * 16 + (jj & 15);
        __half tmp[8];
        if (T < 32) {
            const float* s = W_hh0 + (size_t)R * HH + T * 64 + u * 8;
            #pragma unroll
            for (int e = 0; e < 8; e++) tmp[e] = __float2half(s[e]);
        } else {
            #pragma unroll
            for (int e = 0; e < 8; e++) {
                int c = (T - 32) * 64 + u * 8 + e;
                tmp[e] = __float2half(c < HIN ? W_ih0[(size_t)R * HIN + c] : 0.f);
            }
        }
        size_t dst = ((size_t)(bn * NT0 + T) * 64 + jj) * 64 + ((u ^ (jj & 7)) << 3);
        *reinterpret_cast<uint4*>(g_W0p + dst) = *reinterpret_cast<uint4*>(tmp);
        return;
    }
    i -= S1;
    const int S2 = NCTA * NT1 * 512;
    if (i < S2) {
        int bn = i / (NT1 * 512), r1 = i % (NT1 * 512);
        int T = r1 / 512, r2 = r1 & 511;
        int jj = r2 >> 3, u = r2 & 7;
        int R = (jj >> 4) * HH + bn * 16 + (jj & 15);
        const float* s = (T < 32)
            ? W_hh1 + (size_t)R * HH + T * 64 + u * 8
            : W_ih1 + (size_t)R * HH + (T - 32) * 64 + u * 8;
        __half tmp[8];
        #pragma unroll
        for (int e = 0; e < 8; e++) tmp[e] = __float2half(s[e]);
        size_t dst = ((size_t)(bn * NT1 + T) * 64 + jj) * 64 + ((u ^ (jj & 7)) << 3);
        *reinterpret_cast<uint4*>(g_W1p + dst) = *reinterpret_cast<uint4*>(tmp);
        return;
    }
    i -= S2;
    const int S3 = 2 * 512;
    if (i < S3) {
        int kt = i / 512, r2 = i % 512;
        int r = r2 >> 3, u = r2 & 7;
        int j = kt * 64 + r;
        __half tmp[8];
        #pragma unroll
        for (int e = 0; e < 8; e++) {
            int b = u * 8 + e;
            tmp[e] = __float2half(j < HIN ? inputs[b * HIN + j] : 0.f);
        }
        *reinterpret_cast<uint4*>(g_xT + kt * TILE_H + swz_off(r, u, 0)) =
            *reinterpret_cast<uint4*>(tmp);
        return;
    }
    i -= S3;
    const int S4 = 32 * 512;
    if (i < S4) {
        int kt = i / 512, r2 = i % 512;
        int r = r2 >> 3, u = r2 & 7;
        int j = kt * 64 + r;
        __half tmp[8];
        #pragma unroll
        for (int e = 0; e < 8; e++)
            tmp[e] = __float2half(hiddens[(size_t)(u * 8 + e) * HH + j]);
        *reinterpret_cast<uint4*>(g_h0Ta + kt * TILE_H + swz_off(r, u, 0)) =
            *reinterpret_cast<uint4*>(tmp);
        return;
    }
    i -= S4;
    if (i < S4) {
        int kt = i / 512, r2 = i % 512;
        int r = r2 >> 3, u = r2 & 7;
        int j = kt * 64 + r;
        __half tmp[8];
        #pragma unroll
        for (int e = 0; e < 8; e++)
            tmp[e] = __float2half(hiddens[(size_t)BB * HH + (size_t)(u * 8 + e) * HH + j]);
        *reinterpret_cast<uint4*>(g_h1Ta + kt * TILE_H + swz_off(r, u, 0)) =
            *reinterpret_cast<uint4*>(tmp);
        return;
    }
    i -= S4;
    if (i < G4) { g_bias0[i] = b_ih0[i] + b_hh0[i]; return; }
    i -= G4;
    if (i < G4) { g_bias1[i] = b_ih1[i] + b_hh1[i]; return; }
    i -= G4;
    const int S7 = OUTD * HH / 8;
    if (i < S7) {
        float4 f0 = *reinterpret_cast<const float4*>(fc_w + (size_t)i * 8);
        float4 f1 = *reinterpret_cast<const float4*>(fc_w + (size_t)i * 8 + 4);
        uint4 u;
        *reinterpret_cast<__half2*>(&u.x) = __floats2half2_rn(f0.x, f0.y);
        *reinterpret_cast<__half2*>(&u.y) = __floats2half2_rn(f0.z, f0.w);
        *reinterpret_cast<__half2*>(&u.z) = __floats2half2_rn(f1.x, f1.y);
        *reinterpret_cast<__half2*>(&u.w) = __floats2half2_rn(f1.z, f1.w);
        reinterpret_cast<uint4*>(g_fcwh)[i] = u;
        return;
    }
    i -= S7;
    const int S8 = BB * HH / 4;
    if (i < S8) {
        reinterpret_cast<float4*>(g_c0)[i] =
            reinterpret_cast<const float4*>(cells)[i];
        return;
    }
    i -= S8;
    if (i < S8) {
        reinterpret_cast<float4*>(g_c1)[i] =
            reinterpret_cast<const float4*>(cells + (size_t)BB * HH)[i];
        return;
    }
}

// ---------------- sync primitives ----------------
__device__ __forceinline__ void spin_gpu(unsigned target) {
    unsigned v;
    do {
        asm volatile("ld.acquire.gpu.u32 %0, [%1];" : "=r"(v)
                     : "l"(&g_barcnt) : "memory");
    } while (v < target);
}
__device__ __forceinline__ void consumer_bar() {
    asm volatile("bar.sync 1, 512;" ::: "memory");
}
__device__ __forceinline__ void mbar_init(uint32_t bar, uint32_t cnt) {
    asm volatile("mbarrier.init.shared.b64 [%0], %1;" :: "r"(bar), "r"(cnt) : "memory");
}
__device__ __forceinline__ void mbar_expect_tx(uint32_t bar, uint32_t bytes) {
    asm volatile("mbarrier.arrive.expect_tx.shared.b64 _, [%0], %1;"
                 :: "r"(bar), "r"(bytes) : "memory");
}
__device__ __forceinline__ void mbar_arrive(uint32_t bar) {
    asm volatile("mbarrier.arrive.shared.b64 _, [%0];" :: "r"(bar) : "memory");
}
__device__ __forceinline__ void bulk_g2s(uint32_t dst, const void* src,
                                         uint32_t bytes, uint32_t bar) {
    asm volatile("cp.async.bulk.shared::cluster.global.mbarrier::complete_tx::bytes "
                 "[%0], [%1], %2, [%3];"
                 :: "r"(dst), "l"(src), "r"(bytes), "r"(bar) : "memory");
}
__device__ __forceinline__ void mbar_wait(uint32_t bar, uint32_t parity) {
    asm volatile(
        "{\n\t.reg .pred P;\n"
        "W%=:\n\t"
        "mbarrier.try_wait.parity.acquire.cta.shared::cta.b64 P, [%0], %1, 0x989680;\n\t"
        "@P bra D%=;\n\t"
        "bra W%=;\n"
        "D%=:\n\t}"
        :: "r"(bar), "r"(parity) : "memory");
}
__device__ __forceinline__ void mma16816(float* c, uint32_t a0, uint32_t a1,
                                         uint32_t a2, uint32_t a3,
                                         uint32_t b0, uint32_t b1) {
    asm volatile(
        "mma.sync.aligned.m16n8k16.row.col.f32.f16.f16.f32 "
        "{%0,%1,%2,%3}, {%4,%5,%6,%7}, {%8,%9}, {%0,%1,%2,%3};\n"
        : "+f"(c[0]), "+f"(c[1]), "+f"(c[2]), "+f"(c[3])
        : "r"(a0), "r"(a1), "r"(a2), "r"(a3), "r"(b0), "r"(b1));
}

// ---------------- epilogue: 8-round k-merge (2 m-halves parallel) + LSTM -------
template<bool WRITE_LIN>
__device__ __forceinline__ void epilogue(char* smc, float (*acc)[8][4],
                                         int mh, int kidx,
                                         const float* __restrict__ bias,
                                         float* __restrict__ c_state,
                                         __half* __restrict__ hT_out,
                                         __half* __restrict__ h_lin,
                                         int bn, int tid) {
    float* Gs = reinterpret_cast<float*>(smc + GS_OFF);
    const int lane = tid & 31;
    const int row0 = mh * 32 + (lane >> 2);
    const int cbase = (lane & 3) * 2;

    consumer_bar();
    #pragma unroll
    for (int r = 0; r < 8; r++) {
        if (kidx == r) {
            #pragma unroll
            for (int mi = 0; mi < 2; mi++) {
                int rr = row0 + mi * 16;
                #pragma unroll
                for (int j = 0; j < 8; j++) {
                    int cc = (j >> 1) * 16 + (j & 1) * 8 + cbase;
                    if (r == 0) {
                        Gs[rr * 68 + cc]           = acc[mi][j][0];
                        Gs[rr * 68 + cc + 1]       = acc[mi][j][1];
                        Gs[(rr + 8) * 68 + cc]     = acc[mi][j][2];
                        Gs[(rr + 8) * 68 + cc + 1] = acc[mi][j][3];
                    } else {
                        Gs[rr * 68 + cc]           += acc[mi][j][0];
                        Gs[rr * 68 + cc + 1]       += acc[mi][j][1];
                        Gs[(rr + 8) * 68 + cc]     += acc[mi][j][2];
                        Gs[(rr + 8) * 68 + cc + 1] += acc[mi][j][3];
                    }
                }
            }
        }
        consumer_bar();
    }

    #pragma unroll
    for (int it = 0; it < 2; it++) {
        int sidx = tid + it * 512;
        int b = sidx >> 4, c = sidx & 15;
        int hcol = bn * 16 + c;
        float vi = Gs[b * 68 + c]      + bias[hcol];
        float vf = Gs[b * 68 + 16 + c] + bias[HH + hcol];
        float vg = Gs[b * 68 + 32 + c] + bias[2 * HH + hcol];
        float vo = Gs[b * 68 + 48 + c] + bias[3 * HH + hcol];
        float ii = 1.f / (1.f + __expf(-vi));
        float ff = 1.f / (1.f + __expf(-vf));
        float gg = tanhf(vg);
        float oo = 1.f / (1.f + __expf(-vo));
        int idx = b * HH + hcol;
        float c2 = ff * c_state[idx] + ii * gg;
        c_state[idx] = c2;
        __half hv = __float2half(oo * tanhf(c2));
        int kt = hcol >> 6, r = hcol & 63;
        hT_out[kt * TILE_H + swz_off(r, b >> 3, b & 7)] = hv;
        if (WRITE_LIN) h_lin[idx] = hv;
    }
    consumer_bar();
}

// ---------------- fc phase ----------------
__device__ __forceinline__ void fc_phase(const __half* __restrict__ h1,
                                         const __half* __restrict__ fcw,
                                         const float* __restrict__ fc_b,
                                         float* __restrict__ out,
                                         int t, int tid, int bid) {
    int warp = tid >> 5;
    int gw = bid * 16 + warp;
    int lane = tid & 31;
    for (int task = gw; task < OUTD * BB; task += NCTA * 16) {
        int j = task % OUTD, b = task / OUTD;
        const uint4* w4 = reinterpret_cast<const uint4*>(fcw + (size_t)j * HH);
        const uint4* h4 = reinterpret_cast<const uint4*>(h1 + (size_t)b * HH);
        float s = 0.f;
        #pragma unroll
        for (int it = 0; it < 8; it++) {
            int k = lane + it * 32;
            uint4 wu = w4[k], hu = h4[k];
            const __half2* wp = reinterpret_cast<const __half2*>(&wu);
            const __half2* hp = reinterpret_cast<const __half2*>(&hu);
            #pragma unroll
            for (int e = 0; e < 4; e++) {
                float2 wf = __half22float2(wp[e]);
                float2 hf = __half22float2(hp[e]);
                s += wf.x * hf.x + wf.y * hf.y;
            }
        }
        #pragma unroll
        for (int o = 16; o; o >>= 1) s += __shfl_xor_sync(0xffffffffu, s, o);
        if (lane == 0) {
            float v = s + fc_b[j];
            v = fminf(fmaxf(v, -1.f), 1.f);
            out[(size_t)b * (TT * OUTD) + t * OUTD + j] = v;
            int kt = j >> 6, r = j & 63;
            g_xT[kt * TILE_H + swz_off(r, b >> 3, b & 7)] = __float2half(v);
        }
    }
}

// ---------------- persistent kernel ----------------
__global__ void __launch_bounds__(NTHR, 1)
persist_kernel(const float* __restrict__ fc_b, float* __restrict__ out) {
    extern __shared__ char smc[];
    uint32_t smb = (uint32_t)__cvta_generic_to_shared(smc);
    const int tid = threadIdx.x, bn = blockIdx.x;
    const int lane = tid & 31, warp = tid >> 5;
    const uint32_t fullb  = smb + BAR_OFF;
    const uint32_t emptyb = smb + BAR_OFF + 128;

    if (tid == 0) {
        #pragma unroll
        for (int s = 0; s < NST; s++) {
            mbar_init(fullb + s * 8, 1);
            mbar_init(emptyb + s * 8, 16);
        }
    }
    __syncthreads();

    if (warp == 16) {
        // ------------- producer: 25*49 tiles, continuous stream -------------
        if (lane == 0) {
            const __half* W0 = g_W0p + (size_t)bn * NT0 * TILE_H;
            const __half* W1 = g_W1p + (size_t)bn * NT1 * TILE_H;
            int G = 0;
            auto issue = [&](const __half* act, const __half* wsrc) {
                int s = G % NST;
                if (G >= NST) mbar_wait(emptyb + s * 8, ((G / NST) - 1) & 1);
                mbar_expect_tx(fullb + s * 8, STAGE);
                bulk_g2s(smb + s * STAGE, act, 16384, fullb + s * 8);
                bulk_g2s(smb + s * STAGE + 16384, wsrc, 16384, fullb + s * 8);
                G++;
            };
            for (int t = 0; t < TT; t++) {
                const __half* h0_in = (t & 1) ? g_h0Tb : g_h0Ta;
                const __half* h0_ot = (t & 1) ? g_h0Ta : g_h0Tb;
                const __half* h1_in = (t & 1) ? g_h1Tb : g_h1Ta;
                if (t > 0) spin_gpu((unsigned)(3 * t - 2) * NCTA);
                for (int i = 0; i < 16; i++)
                    issue(h0_in + (size_t)i * 8192, W0 + (size_t)i * 8192);
                if (t > 0) spin_gpu((unsigned)(3 * t) * NCTA);
                issue(g_xT, W0 + (size_t)16 * 8192);
                for (int i = 0; i < 16; i++)
                    issue(h1_in + (size_t)i * 8192, W1 + (size_t)i * 8192);
                spin_gpu((unsigned)(3 * t + 1) * NCTA);
                for (int i = 0; i < 16; i++)
                    issue(h0_ot + (size_t)i * 8192, W1 + (size_t)(16 + i) * 8192);
            }
        }
        return;
    }

    // ------------- consumers: 16 warps, m2 x n1 x k8 split -------------
    // warp -> (mh = warp&1, kidx = warp>>1). Each warp: its 32 batch-rows x
    // all 64 gate-rows x its k16 slice. A read 1x, W read 2x.
    const int mh = warp & 1, kidx = warp >> 1;
    const int blkoff = (kidx >> 2) * 8192;          // which 64-k granule
    const int kkl = (kidx & 3) * 16;                // local k row base in granule
    const int q = lane >> 3;
    const int kbA = (q >> 1) * 8 + (lane & 7);
    const int mc0 = mh * 32 + (q & 1) * 8;
    const int mc1 = mc0 + 16;
    const int aoff0 = ((kkl + kbA) << 7) + (((((mc0 >> 3) ^ (kbA & 7)) << 3)) << 1);
    const int aoff1 = ((kkl + kbA) << 7) + (((((mc1 >> 3) ^ (kbA & 7)) << 3)) << 1);
    const int klane = lane >> 4;
    const int kx = klane + (kkl >> 3);
    int woffs[4];
    #pragma unroll
    for (int n = 0; n < 4; n++) {
        int jj = n * 16 + (lane & 15);
        woffs[n] = (jj << 7) + ((((kx ^ (jj & 7)) << 3)) << 1);
    }

    float acc[2][8][4];
    auto zero_acc = [&]() {
        #pragma unroll
        for (int mi = 0; mi < 2; mi++)
            #pragma unroll
            for (int j = 0; j < 8; j++)
                #pragma unroll
                for (int e = 0; e < 4; e++) acc[mi][j][e] = 0.f;
    };
    auto consume = [&](int t0, int t1) {
        for (int tg = t0; tg < t1; tg++) {
            int s = tg % NST;
            mbar_wait(fullb + s * 8, (tg / NST) & 1);
            uint32_t abuf = smb + s * STAGE + blkoff;
            uint32_t wbuf = smb + s * STAGE + 16384 + blkoff;
            uint32_t a0[4], a1[4], w[4][4];
            asm volatile("ldmatrix.sync.aligned.m8n8.x4.trans.shared.b16 "
                         "{%0,%1,%2,%3}, [%4];\n"
                         : "=r"(a0[0]), "=r"(a0[1]), "=r"(a0[2]), "=r"(a0[3])
                         : "r"(abuf + aoff0));
            asm volatile("ldmatrix.sync.aligned.m8n8.x4.trans.shared.b16 "
                         "{%0,%1,%2,%3}, [%4];\n"
                         : "=r"(a1[0]), "=r"(a1[1]), "=r"(a1[2]), "=r"(a1[3])
                         : "r"(abuf + aoff1));
            #pragma unroll
            for (int n = 0; n < 4; n++) {
                asm volatile("ldmatrix.sync.aligned.m8n8.x4.shared.b16 "
                             "{%0,%1,%2,%3}, [%4];\n"
                             : "=r"(w[n][0]), "=r"(w[n][1]),
                               "=r"(w[n][2]), "=r"(w[n][3])
                             : "r"(wbuf + woffs[n]));
            }
            #pragma unroll
            for (int mi = 0; mi < 2; mi++) {
                uint32_t* a = mi ? a1 : a0;
                #pragma unroll
                for (int n = 0; n < 4; n++) {
                    mma16816(acc[mi][n * 2],     a[0], a[1], a[2], a[3],
                             w[n][0], w[n][2]);
                    mma16816(acc[mi][n * 2 + 1], a[0], a[1], a[2], a[3],
                             w[n][1], w[n][3]);
                }
            }
            if (lane == 0) mbar_arrive(emptyb + s * 8);
        }
    };

    for (int t = 0; t < TT; t++) {
        __half* h0_ot = (t & 1) ? g_h0Ta : g_h0Tb;
        __half* h1_ot = (t & 1) ? g_h1Ta : g_h1Tb;
        int base = t * NTT;
        // cell0
        zero_acc();
        consume(base, base + NT0T);
        epilogue<false>(smc, acc, mh, kidx, g_bias0, g_c0, h0_ot, nullptr, bn, tid);
        if (tid == 0) { __threadfence(); atomicAdd(&g_barcnt, 1u); }
        // cell1
        zero_acc();
        consume(base + NT0T, base + NTT);
        epilogue<true>(smc, acc, mh, kidx, g_bias1, g_c1, h1_ot, g_h1lin, bn, tid);
        if (tid == 0) {
            __threadfence();
            atomicAdd(&g_barcnt, 1u);
            spin_gpu((unsigned)(3 * t + 2) * NCTA);
        }
        consumer_bar();
        fc_phase(g_h1lin, g_fcwh, fc_b, out, t, tid, bn);
        consumer_bar();
        if (tid == 0) { __threadfence(); atomicAdd(&g_barcnt, 1u); }
    }
}

// ---------------- launch ----------------
extern "C" void kernel_launch(void* const* d_in, const int* in_sizes, int n_in,
                              void* d_out, int out_size) {
    (void)in_sizes; (void)n_in; (void)out_size;
    const float* inputs  = (const float*)d_in[0];
    const float* hiddens = (const float*)d_in[1];
    const float* cells   = (const float*)d_in[2];
    const float* W_ih0   = (const float*)d_in[3];
    const float* W_hh0   = (const float*)d_in[4];
    const float* b_ih0   = (const float*)d_in[5];
    const float* b_hh0   = (const float*)d_in[6];
    const float* W_ih1   = (const float*)d_in[7];
    const float* W_hh1   = (const float*)d_in[8];
    const float* b_ih1   = (const float*)d_in[9];
    const float* b_hh1   = (const float*)d_in[10];
    const float* fc_w    = (const float*)d_in[11];
    const float* fc_b    = (const float*)d_in[12];
    float* out = (float*)d_out;

    cudaFuncSetAttribute(persist_kernel,
                         cudaFuncAttributeMaxDynamicSharedMemorySize, SMEM_BYTES);

    const long SETUP_N = 6555136;
    setup_kernel<<<(int)((SETUP_N + 255) / 256), 256>>>(
        inputs, hiddens, cells, W_ih0, W_hh0, b_ih0, b_hh0,
        W_ih1, W_hh1, b_ih1, b_hh1, fc_w);

    persist_kernel<<<NCTA, NTHR, SMEM_BYTES>>>(fc_b, out);
}

// round 15
// speedup vs baseline: 1.0587x; 1.0587x over previous
#include <cuda_runtime.h>
#include <cuda_fp16.h>
#include <cstdint>
#include <math.h>

#define BB   64
#define HH   2048
#define HIN  66
#define TT   25
#define OUTD 66
#define G4   8192
#define NCTA 128
#define NTHR 544        // 16 consumer warps + 1 producer warp
#define NST  3
#define STAGE 65536     // 32KB act + 32KB weight (k=256 tile, 4 granules)
#define GS_OFF (NST * STAGE)          // 196608
#define BAR_OFF (GS_OFF + 17408)
#define SMEM_BYTES (BAR_OFF + 256)
#define NT0  34         // 64-k granules cell0 (hh: 0..31, ih pad: 32..33)
#define NT1  64         // 64-k granules cell1 (hh: 0..31, ih: 32..63)
#define NTPS 25         // k256-tiles per step: 8 hh0 + 1 x(k128) + 8 hh1 + 8 ih1
#define TILE_H 4096     // halves per 64-k granule

// ---------------- device scratch ----------------
__device__ __align__(256) __half g_W0p[NCTA * NT0 * TILE_H];
__device__ __align__(256) __half g_W1p[NCTA * NT1 * TILE_H];
__device__ __align__(256) __half g_xT[2 * TILE_H];
__device__ __align__(256) __half g_h0Ta[32 * TILE_H], g_h0Tb[32 * TILE_H];
__device__ __align__(256) __half g_h1Ta[32 * TILE_H], g_h1Tb[32 * TILE_H];
__device__ __align__(256) __half g_h1lin[BB * HH];
__device__ __align__(256) __half g_fcwh[OUTD * HH];
__device__ __align__(256) float  g_bias0[G4], g_bias1[G4];
__device__ __align__(256) float  g_c0[BB * HH], g_c1[BB * HH];
__device__ unsigned g_barcnt;

__device__ __forceinline__ int swz_off(int row, int u, int e) {
    return row * 64 + ((u ^ (row & 7)) << 3) + e;
}

// ---------------- setup (W0 hh-first; W1 hh-first) ----------------
__global__ void setup_kernel(const float* __restrict__ inputs,
                             const float* __restrict__ hiddens,
                             const float* __restrict__ cells,
                             const float* __restrict__ W_ih0,
                             const float* __restrict__ W_hh0,
                             const float* __restrict__ b_ih0,
                             const float* __restrict__ b_hh0,
                             const float* __restrict__ W_ih1,
                             const float* __restrict__ W_hh1,
                             const float* __restrict__ b_ih1,
                             const float* __restrict__ b_hh1,
                             const float* __restrict__ fc_w) {
    int i = blockIdx.x * blockDim.x + threadIdx.x;
    if (i == 0) g_barcnt = 0;

    const int S1 = NCTA * NT0 * 512;
    if (i < S1) {
        int bn = i / (NT0 * 512), r1 = i % (NT0 * 512);
        int T = r1 / 512, r2 = r1 & 511;
        int jj = r2 >> 3, u = r2 & 7;
        int R = (jj >> 4) * HH + bn * 16 + (jj & 15);
        __half tmp[8];
        if (T < 32) {
            const float* s = W_hh0 + (size_t)R * HH + T * 64 + u * 8;
            #pragma unroll
            for (int e = 0; e < 8; e++) tmp[e] = __float2half(s[e]);
        } else {
            #pragma unroll
            for (int e = 0; e < 8; e++) {
                int c = (T - 32) * 64 + u * 8 + e;
                tmp[e] = __float2half(c < HIN ? W_ih0[(size_t)R * HIN + c] : 0.f);
            }
        }
        size_t dst = ((size_t)(bn * NT0 + T) * 64 + jj) * 64 + ((u ^ (jj & 7)) << 3);
        *reinterpret_cast<uint4*>(g_W0p + dst) = *reinterpret_cast<uint4*>(tmp);
        return;
    }
    i -= S1;
    const int S2 = NCTA * NT1 * 512;
    if (i < S2) {
        int bn = i / (NT1 * 512), r1 = i % (NT1 * 512);
        int T = r1 / 512, r2 = r1 & 511;
        int jj = r2 >> 3, u = r2 & 7;
        int R = (jj >> 4) * HH + bn * 16 + (jj & 15);
        const float* s = (T < 32)
            ? W_hh1 + (size_t)R * HH + T * 64 + u * 8
            : W_ih1 + (size_t)R * HH + (T - 32) * 64 + u * 8;
        __half tmp[8];
        #pragma unroll
        for (int e = 0; e < 8; e++) tmp[e] = __float2half(s[e]);
        size_t dst = ((size_t)(bn * NT1 + T) * 64 + jj) * 64 + ((u ^ (jj & 7)) << 3);
        *reinterpret_cast<uint4*>(g_W1p + dst) = *reinterpret_cast<uint4*>(tmp);
        return;
    }
    i -= S2;
    const int S3 = 2 * 512;
    if (i < S3) {
        int kt = i / 512, r2 = i % 512;
        int r = r2 >> 3, u = r2 & 7;
        int j = kt * 64 + r;
        __half tmp[8];
        #pragma unroll
        for (int e = 0; e < 8; e++) {
            int b = u * 8 + e;
            tmp[e] = __float2half(j < HIN ? inputs[b * HIN + j] : 0.f);
        }
        *reinterpret_cast<uint4*>(g_xT + kt * TILE_H + swz_off(r, u, 0)) =
            *reinterpret_cast<uint4*>(tmp);
        return;
    }
    i -= S3;
    const int S4 = 32 * 512;
    if (i < S4) {
        int kt = i / 512, r2 = i % 512;
        int r = r2 >> 3, u = r2 & 7;
        int j = kt * 64 + r;
        __half tmp[8];
        #pragma unroll
        for (int e = 0; e < 8; e++)
            tmp[e] = __float2half(hiddens[(size_t)(u * 8 + e) * HH + j]);
        *reinterpret_cast<uint4*>(g_h0Ta + kt * TILE_H + swz_off(r, u, 0)) =
            *reinterpret_cast<uint4*>(tmp);
        return;
    }
    i -= S4;
    if (i < S4) {
        int kt = i / 512, r2 = i % 512;
        int r = r2 >> 3, u = r2 & 7;
        int j = kt * 64 + r;
        __half tmp[8];
        #pragma unroll
        for (int e = 0; e < 8; e++)
            tmp[e] = __float2half(hiddens[(size_t)BB * HH + (size_t)(u * 8 + e) * HH + j]);
        *reinterpret_cast<uint4*>(g_h1Ta + kt * TILE_H + swz_off(r, u, 0)) =
            *reinterpret_cast<uint4*>(tmp);
        return;
    }
    i -= S4;
    if (i < G4) { g_bias0[i] = b_ih0[i] + b_hh0[i]; return; }
    i -= G4;
    if (i < G4) { g_bias1[i] = b_ih1[i] + b_hh1[i]; return; }
    i -= G4;
    const int S7 = OUTD * HH / 8;
    if (i < S7) {
        float4 f0 = *reinterpret_cast<const float4*>(fc_w + (size_t)i * 8);
        float4 f1 = *reinterpret_cast<const float4*>(fc_w + (size_t)i * 8 + 4);
        uint4 u;
        *reinterpret_cast<__half2*>(&u.x) = __floats2half2_rn(f0.x, f0.y);
        *reinterpret_cast<__half2*>(&u.y) = __floats2half2_rn(f0.z, f0.w);
        *reinterpret_cast<__half2*>(&u.z) = __floats2half2_rn(f1.x, f1.y);
        *reinterpret_cast<__half2*>(&u.w) = __floats2half2_rn(f1.z, f1.w);
        reinterpret_cast<uint4*>(g_fcwh)[i] = u;
        return;
    }
    i -= S7;
    const int S8 = BB * HH / 4;
    if (i < S8) {
        reinterpret_cast<float4*>(g_c0)[i] =
            reinterpret_cast<const float4*>(cells)[i];
        return;
    }
    i -= S8;
    if (i < S8) {
        reinterpret_cast<float4*>(g_c1)[i] =
            reinterpret_cast<const float4*>(cells + (size_t)BB * HH)[i];
        return;
    }
}

// ---------------- sync primitives ----------------
__device__ __forceinline__ void spin_gpu(unsigned target) {
    unsigned v;
    do {
        asm volatile("ld.acquire.gpu.u32 %0, [%1];" : "=r"(v)
                     : "l"(&g_barcnt) : "memory");
    } while (v < target);
}
__device__ __forceinline__ void consumer_bar() {
    asm volatile("bar.sync 1, 512;" ::: "memory");
}
__device__ __forceinline__ void mbar_init(uint32_t bar, uint32_t cnt) {
    asm volatile("mbarrier.init.shared.b64 [%0], %1;" :: "r"(bar), "r"(cnt) : "memory");
}
__device__ __forceinline__ void mbar_expect_tx(uint32_t bar, uint32_t bytes) {
    asm volatile("mbarrier.arrive.expect_tx.shared.b64 _, [%0], %1;"
                 :: "r"(bar), "r"(bytes) : "memory");
}
__device__ __forceinline__ void mbar_arrive(uint32_t bar) {
    asm volatile("mbarrier.arrive.shared.b64 _, [%0];" :: "r"(bar) : "memory");
}
__device__ __forceinline__ void bulk_g2s(uint32_t dst, const void* src,
                                         uint32_t bytes, uint32_t bar) {
    asm volatile("cp.async.bulk.shared::cluster.global.mbarrier::complete_tx::bytes "
                 "[%0], [%1], %2, [%3];"
                 :: "r"(dst), "l"(src), "r"(bytes), "r"(bar) : "memory");
}
__device__ __forceinline__ void mbar_wait(uint32_t bar, uint32_t parity) {
    asm volatile(
        "{\n\t.reg .pred P;\n"
        "W%=:\n\t"
        "mbarrier.try_wait.parity.acquire.cta.shared::cta.b64 P, [%0], %1, 0x989680;\n\t"
        "@P bra D%=;\n\t"
        "bra W%=;\n"
        "D%=:\n\t}"
        :: "r"(bar), "r"(parity) : "memory");
}
__device__ __forceinline__ void mma16816(float* c, uint32_t a0, uint32_t a1,
                                         uint32_t a2, uint32_t a3,
                                         uint32_t b0, uint32_t b1) {
    asm volatile(
        "mma.sync.aligned.m16n8k16.row.col.f32.f16.f16.f32 "
        "{%0,%1,%2,%3}, {%4,%5,%6,%7}, {%8,%9}, {%0,%1,%2,%3};\n"
        : "+f"(c[0]), "+f"(c[1]), "+f"(c[2]), "+f"(c[3])
        : "r"(a0), "r"(a1), "r"(a2), "r"(a3), "r"(b0), "r"(b1));
}

// ---------------- epilogue: 4-way k-merge + elementwise LSTM ----------------
template<bool WRITE_LIN>
__device__ __forceinline__ void epilogue(char* smc, float (*acc)[4][4],
                                         const float* __restrict__ bias,
                                         float* __restrict__ c_state,
                                         __half* __restrict__ hT_out,
                                         __half* __restrict__ h_lin,
                                         int bn, int tid) {
    float* Gs = reinterpret_cast<float*>(smc + GS_OFF);
    const int lane = tid & 31, warp = tid >> 5;
    const int wg = warp & 3, wm2 = (warp >> 2) & 1, wn2 = warp >> 3;
    const int row0 = wm2 * 32 + (lane >> 2);
    const int col0 = wn2 * 32 + (lane & 3) * 2;

    consumer_bar();
    #pragma unroll
    for (int r = 0; r < 4; r++) {
        if (wg == r) {
            #pragma unroll
            for (int mi = 0; mi < 2; mi++) {
                #pragma unroll
                for (int nt = 0; nt < 4; nt++) {
                    int rr = row0 + mi * 16, cc = col0 + nt * 8;
                    if (r == 0) {
                        Gs[rr * 68 + cc]           = acc[mi][nt][0];
                        Gs[rr * 68 + cc + 1]       = acc[mi][nt][1];
                        Gs[(rr + 8) * 68 + cc]     = acc[mi][nt][2];
                        Gs[(rr + 8) * 68 + cc + 1] = acc[mi][nt][3];
                    } else {
                        Gs[rr * 68 + cc]           += acc[mi][nt][0];
                        Gs[rr * 68 + cc + 1]       += acc[mi][nt][1];
                        Gs[(rr + 8) * 68 + cc]     += acc[mi][nt][2];
                        Gs[(rr + 8) * 68 + cc + 1] += acc[mi][nt][3];
                    }
                }
            }
        }
        consumer_bar();
    }

    #pragma unroll
    for (int it = 0; it < 2; it++) {
        int sidx = tid + it * 512;
        int b = sidx >> 4, c = sidx & 15;
        int hcol = bn * 16 + c;
        float vi = Gs[b * 68 + c]      + bias[hcol];
        float vf = Gs[b * 68 + 16 + c] + bias[HH + hcol];
        float vg = Gs[b * 68 + 32 + c] + bias[2 * HH + hcol];
        float vo = Gs[b * 68 + 48 + c] + bias[3 * HH + hcol];
        float ii = 1.f / (1.f + __expf(-vi));
        float ff = 1.f / (1.f + __expf(-vf));
        float gg = tanhf(vg);
        float oo = 1.f / (1.f + __expf(-vo));
        int idx = b * HH + hcol;
        float c2 = ff * c_state[idx] + ii * gg;
        c_state[idx] = c2;
        __half hv = __float2half(oo * tanhf(c2));
        int kt = hcol >> 6, r = hcol & 63;
        hT_out[kt * TILE_H + swz_off(r, b >> 3, b & 7)] = hv;
        if (WRITE_LIN) h_lin[idx] = hv;
    }
    consumer_bar();
}

// ---------------- fc phase ----------------
__device__ __forceinline__ void fc_phase(const __half* __restrict__ h1,
                                         const __half* __restrict__ fcw,
                                         const float* __restrict__ fc_b,
                                         float* __restrict__ out,
                                         int t, int tid, int bid) {
    int warp = tid >> 5;
    int gw = bid * 16 + warp;
    int lane = tid & 31;
    for (int task = gw; task < OUTD * BB; task += NCTA * 16) {
        int j = task % OUTD, b = task / OUTD;
        const uint4* w4 = reinterpret_cast<const uint4*>(fcw + (size_t)j * HH);
        const uint4* h4 = reinterpret_cast<const uint4*>(h1 + (size_t)b * HH);
        float s = 0.f;
        #pragma unroll
        for (int it = 0; it < 8; it++) {
            int k = lane + it * 32;
            uint4 wu = w4[k], hu = h4[k];
            const __half2* wp = reinterpret_cast<const __half2*>(&wu);
            const __half2* hp = reinterpret_cast<const __half2*>(&hu);
            #pragma unroll
            for (int e = 0; e < 4; e++) {
                float2 wf = __half22float2(wp[e]);
                float2 hf = __half22float2(hp[e]);
                s += wf.x * hf.x + wf.y * hf.y;
            }
        }
        #pragma unroll
        for (int o = 16; o; o >>= 1) s += __shfl_xor_sync(0xffffffffu, s, o);
        if (lane == 0) {
            float v = s + fc_b[j];
            v = fminf(fmaxf(v, -1.f), 1.f);
            out[(size_t)b * (TT * OUTD) + t * OUTD + j] = v;
            int kt = j >> 6, r = j & 63;
            g_xT[kt * TILE_H + swz_off(r, b >> 3, b & 7)] = __float2half(v);
        }
    }
}

// ---------------- persistent kernel ----------------
__global__ void __launch_bounds__(NTHR, 1)
persist_kernel(const float* __restrict__ fc_b, float* __restrict__ out) {
    extern __shared__ char smc[];
    uint32_t smb = (uint32_t)__cvta_generic_to_shared(smc);
    const int tid = threadIdx.x, bn = blockIdx.x;
    const int lane = tid & 31, warp = tid >> 5;
    const uint32_t fullb  = smb + BAR_OFF;
    const uint32_t emptyb = smb + BAR_OFF + 128;

    if (tid == 0) {
        #pragma unroll
        for (int s = 0; s < NST; s++) {
            mbar_init(fullb + s * 8, 1);
            mbar_init(emptyb + s * 8, 16);
        }
    }
    __syncthreads();

    if (warp == 16) {
        // ------------- producer: 25 steps x 25 k256-tiles -------------
        if (lane == 0) {
            const __half* W0 = g_W0p + (size_t)bn * NT0 * TILE_H;
            const __half* W1 = g_W1p + (size_t)bn * NT1 * TILE_H;
            int G = 0;
            auto issue = [&](const __half* act, const __half* wsrc, int gr) {
                int s = G % NST;
                if (G >= NST) mbar_wait(emptyb + s * 8, ((G / NST) - 1) & 1);
                mbar_expect_tx(fullb + s * 8, (uint32_t)gr * 16384);
                bulk_g2s(smb + s * STAGE, act, (uint32_t)gr * 8192, fullb + s * 8);
                bulk_g2s(smb + s * STAGE + 32768, wsrc, (uint32_t)gr * 8192,
                         fullb + s * 8);
                G++;
            };
            for (int t = 0; t < TT; t++) {
                const __half* h0_in = (t & 1) ? g_h0Tb : g_h0Ta;
                const __half* h0_ot = (t & 1) ? g_h0Ta : g_h0Tb;
                const __half* h1_in = (t & 1) ? g_h1Tb : g_h1Ta;
                if (t > 0) spin_gpu((unsigned)(3 * t - 2) * NCTA);
                for (int j = 0; j < 8; j++)          // cell0 hh (8 x k256)
                    issue(h0_in + (size_t)j * 16384, W0 + (size_t)j * 16384, 4);
                if (t > 0) spin_gpu((unsigned)(3 * t) * NCTA);
                issue(g_xT, W0 + (size_t)131072, 2); // x tile (k128)
                for (int j = 0; j < 8; j++)          // cell1 hh
                    issue(h1_in + (size_t)j * 16384, W1 + (size_t)j * 16384, 4);
                spin_gpu((unsigned)(3 * t + 1) * NCTA);
                for (int j = 0; j < 8; j++)          // cell1 ih
                    issue(h0_ot + (size_t)j * 16384,
                          W1 + (size_t)131072 + (size_t)j * 16384, 4);
            }
        }
        return;
    }

    // ------------- consumers: 16 warps, 2m x 2n x 4k split -------------
    const int wg = warp & 3, wm2 = (warp >> 2) & 1, wn2 = warp >> 3;
    const int kk = wg * 16;
    const int q = lane >> 3;
    const int kbA = (q >> 1) * 8 + (lane & 7);
    const int arow = (kk + kbA) << 7;
    const int mc0 = wm2 * 32 + (q & 1) * 8;
    const int mc1 = mc0 + 16;
    const int aoff0 = arow + (((((mc0 >> 3) ^ (kbA & 7)) << 3)) << 1);
    const int aoff1 = arow + (((((mc1 >> 3) ^ (kbA & 7)) << 3)) << 1);
    const int jj0 = wn2 * 32 + (lane & 15);
    const int jj1 = jj0 + 16;
    const int klane = lane >> 4;
    const int woff0 = (jj0 << 7) + (((((klane + wg * 2) ^ (jj0 & 7)) << 3)) << 1);
    const int woff1 = (jj1 << 7) + (((((klane + wg * 2) ^ (jj1 & 7)) << 3)) << 1);

    float acc[2][4][4];
    auto zero_acc = [&]() {
        #pragma unroll
        for (int mi = 0; mi < 2; mi++)
            #pragma unroll
            for (int nt = 0; nt < 4; nt++)
                #pragma unroll
                for (int e = 0; e < 4; e++) acc[mi][nt][e] = 0.f;
    };
    auto consume_tile = [&](int tg, int gr) {
        int s = tg % NST;
        mbar_wait(fullb + s * 8, (tg / NST) & 1);
        uint32_t abase = smb + s * STAGE;
        uint32_t wbase = abase + 32768;
        #pragma unroll 4
        for (int blk = 0; blk < gr; blk++) {
            uint32_t abuf = abase + blk * 8192;
            uint32_t wbuf = wbase + blk * 8192;
            uint32_t a0[4], a1[4], p[4], qq[4];
            asm volatile("ldmatrix.sync.aligned.m8n8.x4.trans.shared.b16 "
                         "{%0,%1,%2,%3}, [%4];\n"
                         : "=r"(a0[0]), "=r"(a0[1]), "=r"(a0[2]), "=r"(a0[3])
                         : "r"(abuf + aoff0));
            asm volatile("ldmatrix.sync.aligned.m8n8.x4.trans.shared.b16 "
                         "{%0,%1,%2,%3}, [%4];\n"
                         : "=r"(a1[0]), "=r"(a1[1]), "=r"(a1[2]), "=r"(a1[3])
                         : "r"(abuf + aoff1));
            asm volatile("ldmatrix.sync.aligned.m8n8.x4.shared.b16 "
                         "{%0,%1,%2,%3}, [%4];\n"
                         : "=r"(p[0]), "=r"(p[1]), "=r"(p[2]), "=r"(p[3])
                         : "r"(wbuf + woff0));
            asm volatile("ldmatrix.sync.aligned.m8n8.x4.shared.b16 "
                         "{%0,%1,%2,%3}, [%4];\n"
                         : "=r"(qq[0]), "=r"(qq[1]), "=r"(qq[2]), "=r"(qq[3])
                         : "r"(wbuf + woff1));
            #pragma unroll
            for (int mi = 0; mi < 2; mi++) {
                uint32_t* a = mi ? a1 : a0;
                mma16816(acc[mi][0], a[0], a[1], a[2], a[3], p[0], p[2]);
                mma16816(acc[mi][1], a[0], a[1], a[2], a[3], p[1], p[3]);
                mma16816(acc[mi][2], a[0], a[1], a[2], a[3], qq[0], qq[2]);
                mma16816(acc[mi][3], a[0], a[1], a[2], a[3], qq[1], qq[3]);
            }
        }
        if (lane == 0) mbar_arrive(emptyb + s * 8);
    };

    for (int t = 0; t < TT; t++) {
        __half* h0_ot = (t & 1) ? g_h0Ta : g_h0Tb;
        __half* h1_ot = (t & 1) ? g_h1Ta : g_h1Tb;
        int base = t * NTPS;
        // cell0: tiles 0..7 (k256) + tile 8 (x, k128)
        zero_acc();
        for (int j = 0; j < 8; j++) consume_tile(base + j, 4);
        consume_tile(base + 8, 2);
        epilogue<false>(smc, acc, g_bias0, g_c0, h0_ot, nullptr, bn, tid);
        if (tid == 0) { __threadfence(); atomicAdd(&g_barcnt, 1u); }
        // cell1: tiles 9..24 (k256)
        zero_acc();
        for (int j = 9; j < NTPS; j++) consume_tile(base + j, 4);
        epilogue<true>(smc, acc, g_bias1, g_c1, h1_ot, g_h1lin, bn, tid);
        if (tid == 0) {
            __threadfence();
            atomicAdd(&g_barcnt, 1u);
            spin_gpu((unsigned)(3 * t + 2) * NCTA);
        }
        consumer_bar();
        fc_phase(g_h1lin, g_fcwh, fc_b, out, t, tid, bn);
        consumer_bar();
        if (tid == 0) { __threadfence(); atomicAdd(&g_barcnt, 1u); }
    }
}

// ---------------- launch ----------------
extern "C" void kernel_launch(void* const* d_in, const int* in_sizes, int n_in,
                              void* d_out, int out_size) {
    (void)in_sizes; (void)n_in; (void)out_size;
    const float* inputs  = (const float*)d_in[0];
    const float* hiddens = (const float*)d_in[1];
    const float* cells   = (const float*)d_in[2];
    const float* W_ih0   = (const float*)d_in[3];
    const float* W_hh0   = (const float*)d_in[4];
    const float* b_ih0   = (const float*)d_in[5];
    const float* b_hh0   = (const float*)d_in[6];
    const float* W_ih1   = (const float*)d_in[7];
    const float* W_hh1   = (const float*)d_in[8];
    const float* b_ih1   = (const float*)d_in[9];
    const float* b_hh1   = (const float*)d_in[10];
    const float* fc_w    = (const float*)d_in[11];
    const float* fc_b    = (const float*)d_in[12];
    float* out = (float*)d_out;

    cudaFuncSetAttribute(persist_kernel,
                         cudaFuncAttributeMaxDynamicSharedMemorySize, SMEM_BYTES);

    const long SETUP_N = 6555136;
    setup_kernel<<<(int)((SETUP_N + 255) / 256), 256>>>(
        inputs, hiddens, cells, W_ih0, W_hh0, b_ih0, b_hh0,
        W_ih1, W_hh1, b_ih1, b_hh1, fc_w);

    persist_kernel<<<NCTA, NTHR, SMEM_BYTES>>>(fc_b, out);
}

// round 16
// speedup vs baseline: 1.0912x; 1.0307x over previous
#include <cuda_runtime.h>
#include <cuda_fp16.h>
#include <cstdint>
#include <math.h>

#define BB   64
#define HH   2048
#define HIN  66
#define TT   25
#define OUTD 66
#define G4   8192
#define NCTA 128
#define NTHR 544        // 16 consumer warps (2 ping-pong groups of 8) + 1 producer
#define NST  6
#define STAGE 32768     // 16KB act + 16KB weight (k=128 tile)
#define GS_OFF (NST * STAGE)
#define BAR_OFF (GS_OFF + 17408)
#define SMEM_BYTES (BAR_OFF + 256)
#define NT0  34         // 64-k granules cell0 (hh first: 0..31, ih: 32..33)
#define NT1  64         // 64-k granules cell1 (hh: 0..31, ih: 32..63)
#define NT0T 17
#define NTT  49
#define TILE_H 4096

// ---------------- device scratch ----------------
__device__ __align__(256) __half g_W0p[NCTA * NT0 * TILE_H];
__device__ __align__(256) __half g_W1p[NCTA * NT1 * TILE_H];
__device__ __align__(256) __half g_xT[2 * TILE_H];
__device__ __align__(256) __half g_h0Ta[32 * TILE_H], g_h0Tb[32 * TILE_H];
__device__ __align__(256) __half g_h1Ta[32 * TILE_H], g_h1Tb[32 * TILE_H];
__device__ __align__(256) __half g_h1lin[BB * HH];
__device__ __align__(256) __half g_fcwh[OUTD * HH];
__device__ __align__(256) float  g_bias0[G4], g_bias1[G4];
__device__ __align__(256) float  g_c0[BB * HH], g_c1[BB * HH];
__device__ unsigned g_barcnt;

__device__ __forceinline__ int swz_off(int row, int u, int e) {
    return row * 64 + ((u ^ (row & 7)) << 3) + e;
}

// ---------------- setup (W0 hh-first; W1 hh-first) ----------------
__global__ void setup_kernel(const float* __restrict__ inputs,
                             const float* __restrict__ hiddens,
                             const float* __restrict__ cells,
                             const float* __restrict__ W_ih0,
                             const float* __restrict__ W_hh0,
                             const float* __restrict__ b_ih0,
                             const float* __restrict__ b_hh0,
                             const float* __restrict__ W_ih1,
                             const float* __restrict__ W_hh1,
                             const float* __restrict__ b_ih1,
                             const float* __restrict__ b_hh1,
                             const float* __restrict__ fc_w) {
    int i = blockIdx.x * blockDim.x + threadIdx.x;
    if (i == 0) g_barcnt = 0;

    const int S1 = NCTA * NT0 * 512;
    if (i < S1) {
        int bn = i / (NT0 * 512), r1 = i % (NT0 * 512);
        int T = r1 / 512, r2 = r1 & 511;
        int jj = r2 >> 3, u = r2 & 7;
        int R = (jj >> 4) * HH + bn * 16 + (jj & 15);
        __half tmp[8];
        if (T < 32) {
            const float* s = W_hh0 + (size_t)R * HH + T * 64 + u * 8;
            #pragma unroll
            for (int e = 0; e < 8; e++) tmp[e] = __float2half(s[e]);
        } else {
            #pragma unroll
            for (int e = 0; e < 8; e++) {
                int c = (T - 32) * 64 + u * 8 + e;
                tmp[e] = __float2half(c < HIN ? W_ih0[(size_t)R * HIN + c] : 0.f);
            }
        }
        size_t dst = ((size_t)(bn * NT0 + T) * 64 + jj) * 64 + ((u ^ (jj & 7)) << 3);
        *reinterpret_cast<uint4*>(g_W0p + dst) = *reinterpret_cast<uint4*>(tmp);
        return;
    }
    i -= S1;
    const int S2 = NCTA * NT1 * 512;
    if (i < S2) {
        int bn = i / (NT1 * 512), r1 = i % (NT1 * 512);
        int T = r1 / 512, r2 = r1 & 511;
        int jj = r2 >> 3, u = r2 & 7;
        int R = (jj >> 4) * HH + bn * 16 + (jj & 15);
        const float* s = (T < 32)
            ? W_hh1 + (size_t)R * HH + T * 64 + u * 8
            : W_ih1 + (size_t)R * HH + (T - 32) * 64 + u * 8;
        __half tmp[8];
        #pragma unroll
        for (int e = 0; e < 8; e++) tmp[e] = __float2half(s[e]);
        size_t dst = ((size_t)(bn * NT1 + T) * 64 + jj) * 64 + ((u ^ (jj & 7)) << 3);
        *reinterpret_cast<uint4*>(g_W1p + dst) = *reinterpret_cast<uint4*>(tmp);
        return;
    }
    i -= S2;
    const int S3 = 2 * 512;
    if (i < S3) {
        int kt = i / 512, r2 = i % 512;
        int r = r2 >> 3, u = r2 & 7;
        int j = kt * 64 + r;
        __half tmp[8];
        #pragma unroll
        for (int e = 0; e < 8; e++) {
            int b = u * 8 + e;
            tmp[e] = __float2half(j < HIN ? inputs[b * HIN + j] : 0.f);
        }
        *reinterpret_cast<uint4*>(g_xT + kt * TILE_H + swz_off(r, u, 0)) =
            *reinterpret_cast<uint4*>(tmp);
        return;
    }
    i -= S3;
    const int S4 = 32 * 512;
    if (i < S4) {
        int kt = i / 512, r2 = i % 512;
        int r = r2 >> 3, u = r2 & 7;
        int j = kt * 64 + r;
        __half tmp[8];
        #pragma unroll
        for (int e = 0; e < 8; e++)
            tmp[e] = __float2half(hiddens[(size_t)(u * 8 + e) * HH + j]);
        *reinterpret_cast<uint4*>(g_h0Ta + kt * TILE_H + swz_off(r, u, 0)) =
            *reinterpret_cast<uint4*>(tmp);
        return;
    }
    i -= S4;
    if (i < S4) {
        int kt = i / 512, r2 = i % 512;
        int r = r2 >> 3, u = r2 & 7;
        int j = kt * 64 + r;
        __half tmp[8];
        #pragma unroll
        for (int e = 0; e < 8; e++)
            tmp[e] = __float2half(hiddens[(size_t)BB * HH + (size_t)(u * 8 + e) * HH + j]);
        *reinterpret_cast<uint4*>(g_h1Ta + kt * TILE_H + swz_off(r, u, 0)) =
            *reinterpret_cast<uint4*>(tmp);
        return;
    }
    i -= S4;
    if (i < G4) { g_bias0[i] = b_ih0[i] + b_hh0[i]; return; }
    i -= G4;
    if (i < G4) { g_bias1[i] = b_ih1[i] + b_hh1[i]; return; }
    i -= G4;
    const int S7 = OUTD * HH / 8;
    if (i < S7) {
        float4 f0 = *reinterpret_cast<const float4*>(fc_w + (size_t)i * 8);
        float4 f1 = *reinterpret_cast<const float4*>(fc_w + (size_t)i * 8 + 4);
        uint4 u;
        *reinterpret_cast<__half2*>(&u.x) = __floats2half2_rn(f0.x, f0.y);
        *reinterpret_cast<__half2*>(&u.y) = __floats2half2_rn(f0.z, f0.w);
        *reinterpret_cast<__half2*>(&u.z) = __floats2half2_rn(f1.x, f1.y);
        *reinterpret_cast<__half2*>(&u.w) = __floats2half2_rn(f1.z, f1.w);
        reinterpret_cast<uint4*>(g_fcwh)[i] = u;
        return;
    }
    i -= S7;
    const int S8 = BB * HH / 4;
    if (i < S8) {
        reinterpret_cast<float4*>(g_c0)[i] =
            reinterpret_cast<const float4*>(cells)[i];
        return;
    }
    i -= S8;
    if (i < S8) {
        reinterpret_cast<float4*>(g_c1)[i] =
            reinterpret_cast<const float4*>(cells + (size_t)BB * HH)[i];
        return;
    }
}

// ---------------- sync primitives ----------------
__device__ __forceinline__ void spin_gpu(unsigned target) {
    unsigned v;
    do {
        asm volatile("ld.acquire.gpu.u32 %0, [%1];" : "=r"(v)
                     : "l"(&g_barcnt) : "memory");
    } while (v < target);
}
__device__ __forceinline__ void consumer_bar() {
    asm volatile("bar.sync 1, 512;" ::: "memory");
}
__device__ __forceinline__ void mbar_init(uint32_t bar, uint32_t cnt) {
    asm volatile("mbarrier.init.shared.b64 [%0], %1;" :: "r"(bar), "r"(cnt) : "memory");
}
__device__ __forceinline__ void mbar_expect_tx(uint32_t bar, uint32_t bytes) {
    asm volatile("mbarrier.arrive.expect_tx.shared.b64 _, [%0], %1;"
                 :: "r"(bar), "r"(bytes) : "memory");
}
__device__ __forceinline__ void mbar_arrive(uint32_t bar) {
    asm volatile("mbarrier.arrive.shared.b64 _, [%0];" :: "r"(bar) : "memory");
}
__device__ __forceinline__ void bulk_g2s(uint32_t dst, const void* src,
                                         uint32_t bytes, uint32_t bar) {
    asm volatile("cp.async.bulk.shared::cluster.global.mbarrier::complete_tx::bytes "
                 "[%0], [%1], %2, [%3];"
                 :: "r"(dst), "l"(src), "r"(bytes), "r"(bar) : "memory");
}
__device__ __forceinline__ void mbar_wait(uint32_t bar, uint32_t parity) {
    asm volatile(
        "{\n\t.reg .pred P;\n"
        "W%=:\n\t"
        "mbarrier.try_wait.parity.acquire.cta.shared::cta.b64 P, [%0], %1, 0x989680;\n\t"
        "@P bra D%=;\n\t"
        "bra W%=;\n"
        "D%=:\n\t}"
        :: "r"(bar), "r"(parity) : "memory");
}
__device__ __forceinline__ void mma16816(float* c, uint32_t a0, uint32_t a1,
                                         uint32_t a2, uint32_t a3,
                                         uint32_t b0, uint32_t b1) {
    asm volatile(
        "mma.sync.aligned.m16n8k16.row.col.f32.f16.f16.f32 "
        "{%0,%1,%2,%3}, {%4,%5,%6,%7}, {%8,%9}, {%0,%1,%2,%3};\n"
        : "+f"(c[0]), "+f"(c[1]), "+f"(c[2]), "+f"(c[3])
        : "r"(a0), "r"(a1), "r"(a2), "r"(a3), "r"(b0), "r"(b1));
}

// ---------------- epilogue: 4-way partial merge + elementwise LSTM ----------
// partials: id = grp*2 + kh  (2 ping-pong groups x k2 split)
template<bool WRITE_LIN>
__device__ __forceinline__ void epilogue(char* smc, float (*acc)[4][4],
                                         int id, int wm2, int wn2,
                                         const float* __restrict__ bias,
                                         float* __restrict__ c_state,
                                         __half* __restrict__ hT_out,
                                         __half* __restrict__ h_lin,
                                         int bn, int tid) {
    float* Gs = reinterpret_cast<float*>(smc + GS_OFF);
    const int lane = tid & 31;
    const int row0 = wm2 * 32 + (lane >> 2);
    const int col0 = wn2 * 32 + (lane & 3) * 2;

    consumer_bar();
    #pragma unroll
    for (int r = 0; r < 4; r++) {
        if (id == r) {
            #pragma unroll
            for (int mi = 0; mi < 2; mi++) {
                #pragma unroll
                for (int nt = 0; nt < 4; nt++) {
                    int rr = row0 + mi * 16, cc = col0 + nt * 8;
                    if (r == 0) {
                        Gs[rr * 68 + cc]           = acc[mi][nt][0];
                        Gs[rr * 68 + cc + 1]       = acc[mi][nt][1];
                        Gs[(rr + 8) * 68 + cc]     = acc[mi][nt][2];
                        Gs[(rr + 8) * 68 + cc + 1] = acc[mi][nt][3];
                    } else {
                        Gs[rr * 68 + cc]           += acc[mi][nt][0];
                        Gs[rr * 68 + cc + 1]       += acc[mi][nt][1];
                        Gs[(rr + 8) * 68 + cc]     += acc[mi][nt][2];
                        Gs[(rr + 8) * 68 + cc + 1] += acc[mi][nt][3];
                    }
                }
            }
        }
        consumer_bar();
    }

    #pragma unroll
    for (int it = 0; it < 2; it++) {
        int sidx = tid + it * 512;
        int b = sidx >> 4, c = sidx & 15;
        int hcol = bn * 16 + c;
        float vi = Gs[b * 68 + c]      + bias[hcol];
        float vf = Gs[b * 68 + 16 + c] + bias[HH + hcol];
        float vg = Gs[b * 68 + 32 + c] + bias[2 * HH + hcol];
        float vo = Gs[b * 68 + 48 + c] + bias[3 * HH + hcol];
        float ii = 1.f / (1.f + __expf(-vi));
        float ff = 1.f / (1.f + __expf(-vf));
        float gg = tanhf(vg);
        float oo = 1.f / (1.f + __expf(-vo));
        int idx = b * HH + hcol;
        float c2 = ff * c_state[idx] + ii * gg;
        c_state[idx] = c2;
        __half hv = __float2half(oo * tanhf(c2));
        int kt = hcol >> 6, r = hcol & 63;
        hT_out[kt * TILE_H + swz_off(r, b >> 3, b & 7)] = hv;
        if (WRITE_LIN) h_lin[idx] = hv;
    }
    consumer_bar();
}

// ---------------- fc phase ----------------
__device__ __forceinline__ void fc_phase(const __half* __restrict__ h1,
                                         const __half* __restrict__ fcw,
                                         const float* __restrict__ fc_b,
                                         float* __restrict__ out,
                                         int t, int tid, int bid) {
    int warp = tid >> 5;
    int gw = bid * 16 + warp;
    int lane = tid & 31;
    for (int task = gw; task < OUTD * BB; task += NCTA * 16) {
        int j = task % OUTD, b = task / OUTD;
        const uint4* w4 = reinterpret_cast<const uint4*>(fcw + (size_t)j * HH);
        const uint4* h4 = reinterpret_cast<const uint4*>(h1 + (size_t)b * HH);
        float s = 0.f;
        #pragma unroll
        for (int it = 0; it < 8; it++) {
            int k = lane + it * 32;
            uint4 wu = w4[k], hu = h4[k];
            const __half2* wp = reinterpret_cast<const __half2*>(&wu);
            const __half2* hp = reinterpret_cast<const __half2*>(&hu);
            #pragma unroll
            for (int e = 0; e < 4; e++) {
                float2 wf = __half22float2(wp[e]);
                float2 hf = __half22float2(hp[e]);
                s += wf.x * hf.x + wf.y * hf.y;
            }
        }
        #pragma unroll
        for (int o = 16; o; o >>= 1) s += __shfl_xor_sync(0xffffffffu, s, o);
        if (lane == 0) {
            float v = s + fc_b[j];
            v = fminf(fmaxf(v, -1.f), 1.f);
            out[(size_t)b * (TT * OUTD) + t * OUTD + j] = v;
            int kt = j >> 6, r = j & 63;
            g_xT[kt * TILE_H + swz_off(r, b >> 3, b & 7)] = __float2half(v);
        }
    }
}

// ---------------- persistent kernel ----------------
__global__ void __launch_bounds__(NTHR, 1)
persist_kernel(const float* __restrict__ fc_b, float* __restrict__ out) {
    extern __shared__ char smc[];
    uint32_t smb = (uint32_t)__cvta_generic_to_shared(smc);
    const int tid = threadIdx.x, bn = blockIdx.x;
    const int lane = tid & 31, warp = tid >> 5;
    const uint32_t fullb  = smb + BAR_OFF;
    const uint32_t emptyb = smb + BAR_OFF + 128;

    if (tid == 0) {
        #pragma unroll
        for (int s = 0; s < NST; s++) {
            mbar_init(fullb + s * 8, 1);
            mbar_init(emptyb + s * 8, 8);   // one ping-pong group per stage
        }
    }
    __syncthreads();

    if (warp == 16) {
        // ------------- producer: 25*49 tiles, continuous stream -------------
        if (lane == 0) {
            const __half* W0 = g_W0p + (size_t)bn * NT0 * TILE_H;
            const __half* W1 = g_W1p + (size_t)bn * NT1 * TILE_H;
            int G = 0;
            auto issue = [&](const __half* act, const __half* wsrc) {
                int s = G % NST;
                if (G >= NST) mbar_wait(emptyb + s * 8, ((G / NST) - 1) & 1);
                mbar_expect_tx(fullb + s * 8, STAGE);
                bulk_g2s(smb + s * STAGE, act, 16384, fullb + s * 8);
                bulk_g2s(smb + s * STAGE + 16384, wsrc, 16384, fullb + s * 8);
                G++;
            };
            for (int t = 0; t < TT; t++) {
                const __half* h0_in = (t & 1) ? g_h0Tb : g_h0Ta;
                const __half* h0_ot = (t & 1) ? g_h0Ta : g_h0Tb;
                const __half* h1_in = (t & 1) ? g_h1Tb : g_h1Ta;
                if (t > 0) spin_gpu((unsigned)(3 * t - 2) * NCTA);
                for (int i = 0; i < 16; i++)
                    issue(h0_in + (size_t)i * 8192, W0 + (size_t)i * 8192);
                if (t > 0) spin_gpu((unsigned)(3 * t) * NCTA);
                issue(g_xT, W0 + (size_t)16 * 8192);
                for (int i = 0; i < 16; i++)
                    issue(h1_in + (size_t)i * 8192, W1 + (size_t)i * 8192);
                spin_gpu((unsigned)(3 * t + 1) * NCTA);
                for (int i = 0; i < 16; i++)
                    issue(h0_ot + (size_t)i * 8192, W1 + (size_t)(16 + i) * 8192);
            }
        }
        return;
    }

    // ------------- consumers: 2 ping-pong groups of 8 (m2 x n2 x k2) ---------
    const int grp = warp >> 3;                  // 0: even tiles, 1: odd tiles
    const int wl  = warp & 7;
    const int kh  = wl & 1;                     // k-half within granule
    const int wm2 = (wl >> 1) & 1;
    const int wn2 = wl >> 2;
    const int id  = grp * 2 + kh;               // merge-partial id (0..3)

    const int q = lane >> 3;
    const int kbA = (q >> 1) * 8 + (lane & 7);
    const int mc0 = wm2 * 32 + (q & 1) * 8;
    const int mc1 = mc0 + 16;
    const int swzA0 = ((((mc0 >> 3) ^ (kbA & 7)) << 3)) << 1;
    const int swzA1 = ((((mc1 >> 3) ^ (kbA & 7)) << 3)) << 1;
    const int jj0 = wn2 * 32 + (lane & 15);
    const int jj1 = jj0 + 16;
    const int klane = lane >> 4;
    const int jm0 = jj0 & 7, jm1 = jj1 & 7;

    float acc[2][4][4];
    auto zero_acc = [&]() {
        #pragma unroll
        for (int mi = 0; mi < 2; mi++)
            #pragma unroll
            for (int nt = 0; nt < 4; nt++)
                #pragma unroll
                for (int e = 0; e < 4; e++) acc[mi][nt][e] = 0.f;
    };
    auto consume = [&](int t0, int t1) {
        for (int tg = t0; tg < t1; tg++) {
            if ((tg & 1) != grp) continue;      // ping-pong tile ownership
            int s = tg % NST;
            mbar_wait(fullb + s * 8, (tg / NST) & 1);
            uint32_t abase = smb + s * STAGE;
            uint32_t wbase = abase + 16384;
            #pragma unroll
            for (int blk = 0; blk < 2; blk++) {
                uint32_t abuf = abase + blk * 8192;
                uint32_t wbuf = wbase + blk * 8192;
                #pragma unroll
                for (int st = 0; st < 2; st++) {
                    int kk = kh * 32 + st * 16;
                    uint32_t a0[4], a1[4], p[4], qq[4];
                    asm volatile("ldmatrix.sync.aligned.m8n8.x4.trans.shared.b16 "
                                 "{%0,%1,%2,%3}, [%4];\n"
                                 : "=r"(a0[0]), "=r"(a0[1]), "=r"(a0[2]), "=r"(a0[3])
                                 : "r"(abuf + ((kk + kbA) << 7) + swzA0));
                    asm volatile("ldmatrix.sync.aligned.m8n8.x4.trans.shared.b16 "
                                 "{%0,%1,%2,%3}, [%4];\n"
                                 : "=r"(a1[0]), "=r"(a1[1]), "=r"(a1[2]), "=r"(a1[3])
                                 : "r"(abuf + ((kk + kbA) << 7) + swzA1));
                    int kx = klane + (kk >> 3);
                    asm volatile("ldmatrix.sync.aligned.m8n8.x4.shared.b16 "
                                 "{%0,%1,%2,%3}, [%4];\n"
                                 : "=r"(p[0]), "=r"(p[1]), "=r"(p[2]), "=r"(p[3])
                                 : "r"(wbuf + (jj0 << 7) + ((((kx ^ jm0) << 3)) << 1)));
                    asm volatile("ldmatrix.sync.aligned.m8n8.x4.shared.b16 "
                                 "{%0,%1,%2,%3}, [%4];\n"
                                 : "=r"(qq[0]), "=r"(qq[1]), "=r"(qq[2]), "=r"(qq[3])
                                 : "r"(wbuf + (jj1 << 7) + ((((kx ^ jm1) << 3)) << 1)));
                    #pragma unroll
                    for (int mi = 0; mi < 2; mi++) {
                        uint32_t* a = mi ? a1 : a0;
                        mma16816(acc[mi][0], a[0], a[1], a[2], a[3], p[0], p[2]);
                        mma16816(acc[mi][1], a[0], a[1], a[2], a[3], p[1], p[3]);
                        mma16816(acc[mi][2], a[0], a[1], a[2], a[3], qq[0], qq[2]);
                        mma16816(acc[mi][3], a[0], a[1], a[2], a[3], qq[1], qq[3]);
                    }
                }
            }
            if (lane == 0) mbar_arrive(emptyb + s * 8);
        }
    };

    for (int t = 0; t < TT; t++) {
        __half* h0_ot = (t & 1) ? g_h0Ta : g_h0Tb;
        __half* h1_ot = (t & 1) ? g_h1Ta : g_h1Tb;
        int base = t * NTT;
        // cell0
        zero_acc();
        consume(base, base + NT0T);
        epilogue<false>(smc, acc, id, wm2, wn2, g_bias0, g_c0, h0_ot,
                        nullptr, bn, tid);
        if (tid == 0) { __threadfence(); atomicAdd(&g_barcnt, 1u); }
        // cell1
        zero_acc();
        consume(base + NT0T, base + NTT);
        epilogue<true>(smc, acc, id, wm2, wn2, g_bias1, g_c1, h1_ot,
                       g_h1lin, bn, tid);
        if (tid == 0) {
            __threadfence();
            atomicAdd(&g_barcnt, 1u);
            spin_gpu((unsigned)(3 * t + 2) * NCTA);
        }
        consumer_bar();
        fc_phase(g_h1lin, g_fcwh, fc_b, out, t, tid, bn);
        consumer_bar();
        if (tid == 0) { __threadfence(); atomicAdd(&g_barcnt, 1u); }
    }
}

// ---------------- launch ----------------
extern "C" void kernel_launch(void* const* d_in, const int* in_sizes, int n_in,
                              void* d_out, int out_size) {
    (void)in_sizes; (void)n_in; (void)out_size;
    const float* inputs  = (const float*)d_in[0];
    const float* hiddens = (const float*)d_in[1];
    const float* cells   = (const float*)d_in[2];
    const float* W_ih0   = (const float*)d_in[3];
    const float* W_hh0   = (const float*)d_in[4];
    const float* b_ih0   = (const float*)d_in[5];
    const float* b_hh0   = (const float*)d_in[6];
    const float* W_ih1   = (const float*)d_in[7];
    const float* W_hh1   = (const float*)d_in[8];
    const float* b_ih1   = (const float*)d_in[9];
    const float* b_hh1   = (const float*)d_in[10];
    const float* fc_w    = (const float*)d_in[11];
    const float* fc_b    = (const float*)d_in[12];
    float* out = (float*)d_out;

    cudaFuncSetAttribute(persist_kernel,
                         cudaFuncAttributeMaxDynamicSharedMemorySize, SMEM_BYTES);

    const long SETUP_N = 6555136;
    setup_kernel<<<(int)((SETUP_N + 255) / 256), 256>>>(
        inputs, hiddens, cells, W_ih0, W_hh0, b_ih0, b_hh0,
        W_ih1, W_hh1, b_ih1, b_hh1, fc_w);

    persist_kernel<<<NCTA, NTHR, SMEM_BYTES>>>(fc_b, out);
}